// round 1
// baseline (speedup 1.0000x reference)
#include <cuda_runtime.h>

// Problem constants
#define Bc  2
#define Sc  2048
#define Dc  512
#define Hc  8
#define DKc 64

// Scratch (no cudaMalloc allowed)
__device__ float g_q[Bc*Sc*Dc];
__device__ float g_k[Bc*Sc*Dc];
__device__ float g_v[Bc*Sc*Dc];
__device__ float g_x[Bc*Sc*Dc];

// ---------------------------------------------------------------------------
// GEMM with bias: C[m,n] = sum_k A[m,k] * W[n,k] + bias[n]
// A: [M,K] row-major, W: [N,K] row-major (torch Linear weight)
// ---------------------------------------------------------------------------
#define GBM 128
#define GBN 64
#define GBK 16
#define GTM 8
#define GTN 4
#define GSTRA (GBM + 4)
#define GSTRW (GBN + 4)

__global__ __launch_bounds__(256) void gemm_bias_kernel(
    const float* __restrict__ A, const float* __restrict__ W,
    const float* __restrict__ bias, float* __restrict__ C,
    int M, int N, int K)
{
    __shared__ float As[GBK][GSTRA];   // As[k][m]
    __shared__ float Ws[GBK][GSTRW];   // Ws[k][n]

    const int tid = threadIdx.x;
    const int tx = tid & 15;           // 0..15 -> n micro
    const int ty = tid >> 4;           // 0..15 -> m micro
    const int m0 = blockIdx.y * GBM;
    const int n0 = blockIdx.x * GBN;

    float acc[GTM][GTN];
    #pragma unroll
    for (int i = 0; i < GTM; ++i)
        #pragma unroll
        for (int j = 0; j < GTN; ++j) acc[i][j] = 0.f;

    for (int k0 = 0; k0 < K; k0 += GBK) {
        // load A tile: GBM x GBK (k contiguous in gmem) -> As[k][m]
        #pragma unroll
        for (int i = 0; i < (GBM * GBK) / 256; ++i) {
            int idx = tid + i * 256;
            int k = idx & (GBK - 1);
            int m = idx >> 4;
            As[k][m] = A[(size_t)(m0 + m) * K + k0 + k];
        }
        // load W tile: GBN x GBK -> Ws[k][n]
        #pragma unroll
        for (int i = 0; i < (GBN * GBK) / 256; ++i) {
            int idx = tid + i * 256;
            int k = idx & (GBK - 1);
            int n = idx >> 4;
            Ws[k][n] = W[(size_t)(n0 + n) * K + k0 + k];
        }
        __syncthreads();

        #pragma unroll
        for (int k = 0; k < GBK; ++k) {
            float a[GTM], w[GTN];
            #pragma unroll
            for (int i = 0; i < GTM; ++i) a[i] = As[k][ty * GTM + i];
            #pragma unroll
            for (int j = 0; j < GTN; ++j) w[j] = Ws[k][tx * GTN + j];
            #pragma unroll
            for (int i = 0; i < GTM; ++i)
                #pragma unroll
                for (int j = 0; j < GTN; ++j)
                    acc[i][j] += a[i] * w[j];
        }
        __syncthreads();
    }

    #pragma unroll
    for (int i = 0; i < GTM; ++i) {
        int m = m0 + ty * GTM + i;
        #pragma unroll
        for (int j = 0; j < GTN; ++j) {
            int n = n0 + tx * GTN + j;
            C[(size_t)m * N + n] = acc[i][j] + bias[n];
        }
    }
}

// ---------------------------------------------------------------------------
// Causal flash attention over projected q/k/v, layout [B,S,D] with heads
// packed: head h occupies columns h*DK .. h*DK+63.
// One CTA = (batch*head, q-tile of 64 rows), 256 threads.
// Thread (r = tid/4, cg = tid%4): query row r, keys k = cg + 4*kk (kk<16),
// output dims d = cg*16 .. cg*16+15.
// ---------------------------------------------------------------------------
#define ABQ 64
#define ABK 64
#define ASTR 68           // padded row stride (floats), 16B-aligned rows
#define ATT_SMEM (3 * 64 * ASTR * 4)

__global__ __launch_bounds__(256) void attn_kernel(
    const float* __restrict__ Q, const float* __restrict__ K,
    const float* __restrict__ V, float* __restrict__ X)
{
    extern __shared__ float sm[];
    float* Qs = sm;                    // [64][ASTR]
    float* Ks = sm + 64 * ASTR;        // [64][ASTR], reused for P tile
    float* Vs = sm + 2 * 64 * ASTR;    // [64][ASTR]

    const int tid = threadIdx.x;
    const int r  = tid >> 2;           // query row within tile
    const int cg = tid & 3;            // column group
    const int q0 = blockIdx.x * ABQ;
    const int bh = blockIdx.y;
    const int b  = bh >> 3;
    const int h  = bh & 7;

    const size_t bbase = (size_t)b * Sc * Dc + (size_t)h * DKc;
    const float* Qb = Q + bbase;
    const float* Kb = K + bbase;
    const float* Vb = V + bbase;

    // load Q tile (rows q0..q0+63, 64 head dims, row stride Dc)
    for (int i = tid; i < 64 * 64; i += 256) {
        int rr = i >> 6, cc = i & 63;
        Qs[rr * ASTR + cc] = Qb[(size_t)(q0 + rr) * Dc + cc];
    }

    float mrow = -1e30f, lrow = 0.f;
    float4 o0 = {0,0,0,0}, o1 = {0,0,0,0}, o2 = {0,0,0,0}, o3 = {0,0,0,0};

    const int ntiles = q0 / ABK + 1;   // causal: skip fully-masked tiles
    for (int t = 0; t < ntiles; ++t) {
        const int k0 = t * ABK;
        __syncthreads();               // prev-iter reads done; also Q visible (t=0)
        for (int i = tid; i < 64 * 64; i += 256) {
            int rr = i >> 6, cc = i & 63;
            Ks[rr * ASTR + cc] = Kb[(size_t)(k0 + rr) * Dc + cc];
            Vs[rr * ASTR + cc] = Vb[(size_t)(k0 + rr) * Dc + cc];
        }
        __syncthreads();

        // scores s[kk] = q_row . k_(cg+4kk)
        float s[16];
        #pragma unroll
        for (int kk = 0; kk < 16; ++kk) s[kk] = 0.f;
        const float4* Qr = (const float4*)(Qs + r * ASTR);
        #pragma unroll
        for (int d4 = 0; d4 < 16; ++d4) {
            float4 q4 = Qr[d4];
            #pragma unroll
            for (int kk = 0; kk < 16; ++kk) {
                const float4 k4 = *(const float4*)(Ks + (cg + 4 * kk) * ASTR + d4 * 4);
                s[kk] += q4.x * k4.x + q4.y * k4.y + q4.z * k4.z + q4.w * k4.w;
            }
        }

        // scale + causal mask + tile max
        float tmax = -1e30f;
        #pragma unroll
        for (int kk = 0; kk < 16; ++kk) {
            int kg = k0 + cg + 4 * kk;
            float sv = s[kk] * 0.125f;               // 1/sqrt(64)
            if (kg > q0 + r) sv = -1e9f;             // matches reference MASK_VALUE
            s[kk] = sv;
            tmax = fmaxf(tmax, sv);
        }
        tmax = fmaxf(tmax, __shfl_xor_sync(0xffffffffu, tmax, 1));
        tmax = fmaxf(tmax, __shfl_xor_sync(0xffffffffu, tmax, 2));

        const float mnew = fmaxf(mrow, tmax);
        const float alpha = __expf(mrow - mnew);
        float psum = 0.f;
        #pragma unroll
        for (int kk = 0; kk < 16; ++kk) {
            float p = __expf(s[kk] - mnew);
            s[kk] = p;
            psum += p;
        }
        psum += __shfl_xor_sync(0xffffffffu, psum, 1);
        psum += __shfl_xor_sync(0xffffffffu, psum, 2);
        lrow = lrow * alpha + psum;
        mrow = mnew;

        o0.x *= alpha; o0.y *= alpha; o0.z *= alpha; o0.w *= alpha;
        o1.x *= alpha; o1.y *= alpha; o1.z *= alpha; o1.w *= alpha;
        o2.x *= alpha; o2.y *= alpha; o2.z *= alpha; o2.w *= alpha;
        o3.x *= alpha; o3.y *= alpha; o3.z *= alpha; o3.w *= alpha;

        __syncthreads();               // everyone done reading Ks
        #pragma unroll
        for (int kk = 0; kk < 16; ++kk)
            Ks[r * ASTR + cg + 4 * kk] = s[kk];      // P tile overwrites Ks
        __syncthreads();

        // O += P @ V  (thread covers d = cg*16 .. cg*16+15)
        const float* Pr = Ks + r * ASTR;
        const float* Vcol = Vs + cg * 16;
        #pragma unroll 8
        for (int k = 0; k < 64; ++k) {
            float p = Pr[k];
            const float4* Vr = (const float4*)(Vcol + k * ASTR);
            float4 v0 = Vr[0], v1 = Vr[1], v2 = Vr[2], v3 = Vr[3];
            o0.x += p * v0.x; o0.y += p * v0.y; o0.z += p * v0.z; o0.w += p * v0.w;
            o1.x += p * v1.x; o1.y += p * v1.y; o1.z += p * v1.z; o1.w += p * v1.w;
            o2.x += p * v2.x; o2.y += p * v2.y; o2.z += p * v2.z; o2.w += p * v2.w;
            o3.x += p * v3.x; o3.y += p * v3.y; o3.z += p * v3.z; o3.w += p * v3.w;
        }
    }

    const float inv = 1.f / lrow;
    float4* Xr = (float4*)(X + ((size_t)b * Sc + q0 + r) * Dc + (size_t)h * DKc + cg * 16);
    float4 w0 = {o0.x*inv, o0.y*inv, o0.z*inv, o0.w*inv};
    float4 w1 = {o1.x*inv, o1.y*inv, o1.z*inv, o1.w*inv};
    float4 w2 = {o2.x*inv, o2.y*inv, o2.z*inv, o2.w*inv};
    float4 w3 = {o3.x*inv, o3.y*inv, o3.z*inv, o3.w*inv};
    Xr[0] = w0; Xr[1] = w1; Xr[2] = w2; Xr[3] = w3;
}

// ---------------------------------------------------------------------------
// Launch
// ---------------------------------------------------------------------------
extern "C" void kernel_launch(void* const* d_in, const int* in_sizes, int n_in,
                              void* d_out, int out_size)
{
    const float* query = (const float*)d_in[0];
    const float* key_  = (const float*)d_in[1];
    const float* value = (const float*)d_in[2];
    // d_in[3] = mask (tril, deterministic) -> implemented as causal indexing
    const float* Wq = (const float*)d_in[4];
    const float* bq = (const float*)d_in[5];
    const float* Wk = (const float*)d_in[6];
    const float* bk = (const float*)d_in[7];
    const float* Wv = (const float*)d_in[8];
    const float* bv = (const float*)d_in[9];
    const float* Wo = (const float*)d_in[10];
    const float* bo = (const float*)d_in[11];
    float* out = (float*)d_out;

    float *q_buf, *k_buf, *v_buf, *x_buf;
    cudaGetSymbolAddress((void**)&q_buf, g_q);
    cudaGetSymbolAddress((void**)&k_buf, g_k);
    cudaGetSymbolAddress((void**)&v_buf, g_v);
    cudaGetSymbolAddress((void**)&x_buf, g_x);

    cudaFuncSetAttribute(attn_kernel,
                         cudaFuncAttributeMaxDynamicSharedMemorySize, ATT_SMEM);

    const int M = Bc * Sc;     // 4096
    const int N = Dc;          // 512
    const int K = Dc;          // 512
    dim3 ggrid(N / GBN, M / GBM);   // (8, 32)

    gemm_bias_kernel<<<ggrid, 256>>>(query, Wq, bq, q_buf, M, N, K);
    gemm_bias_kernel<<<ggrid, 256>>>(key_,  Wk, bk, k_buf, M, N, K);
    gemm_bias_kernel<<<ggrid, 256>>>(value, Wv, bv, v_buf, M, N, K);

    dim3 agrid(Sc / ABQ, Bc * Hc);  // (32, 16)
    attn_kernel<<<agrid, 256, ATT_SMEM>>>(q_buf, k_buf, v_buf, x_buf);

    gemm_bias_kernel<<<ggrid, 256>>>(x_buf, Wo, bo, out, M, N, K);
}

// round 2
// speedup vs baseline: 5.8570x; 5.8570x over previous
#include <cuda_runtime.h>
#include <cstdint>

#define Bc  2
#define Sc  2048
#define Dc  512
#define Hc  8

// Scratch (no cudaMalloc allowed)
__device__ float g_q[Bc*Sc*Dc];
__device__ float g_k[Bc*Sc*Dc];
__device__ float g_v[Bc*Sc*Dc];
__device__ float g_x[Bc*Sc*Dc];

// ---------------------------------------------------------------------------
// helpers
// ---------------------------------------------------------------------------
__device__ __forceinline__ uint32_t f2tf(float f) {
    uint32_t r; asm("cvt.rna.tf32.f32 %0, %1;" : "=r"(r) : "f"(f)); return r;
}

__device__ __forceinline__ void mma_tf32(float* c, const uint32_t* a, const uint32_t* b) {
    asm volatile("mma.sync.aligned.m16n8k8.row.col.f32.tf32.tf32.f32 "
        "{%0,%1,%2,%3}, {%4,%5,%6,%7}, {%8,%9}, {%0,%1,%2,%3};"
        : "+f"(c[0]), "+f"(c[1]), "+f"(c[2]), "+f"(c[3])
        : "r"(a[0]), "r"(a[1]), "r"(a[2]), "r"(a[3]), "r"(b[0]), "r"(b[1]));
}

__device__ __forceinline__ void cp16(uint32_t s, const void* g) {
    asm volatile("cp.async.cg.shared.global [%0], [%1], 16;" :: "r"(s), "l"(g) : "memory");
}
__device__ __forceinline__ void cp_commit() {
    asm volatile("cp.async.commit_group;" ::: "memory");
}

// ---------------------------------------------------------------------------
// TF32 GEMM with bias: C[m,n] = sum_k A[m,k]*W[n,k] + bias[n]
// M=4096, N=512, K=512. Tile 128x64x32, 8 warps (4m x 2n), warp tile 32x32.
// ---------------------------------------------------------------------------
#define GBM 128
#define GBN 64
#define GBK 32
#define GSTR 36                       // 36 mod 32 == 4 -> conflict-free frags
#define GW_OFF (GBM*GSTR)             // 4608 floats
#define GBUF   (GBM*GSTR + GBN*GSTR)  // 6912 floats per buffer
#define GEMM_SMEM (2*GBUF*4)          // 55296 bytes

__global__ __launch_bounds__(256) void gemm_tf32(
    const float* __restrict__ A, const float* __restrict__ W,
    const float* __restrict__ bias, float* __restrict__ C)
{
    extern __shared__ float sm[];
    const int tid  = threadIdx.x;
    const int lane = tid & 31, warp = tid >> 5;
    const int g = lane >> 2, t = lane & 3;
    const int wm = (warp >> 1) * 32, wn = (warp & 1) * 32;
    const int m0 = blockIdx.y * GBM, n0 = blockIdx.x * GBN;

    float acc[2][4][4] = {};

    auto load_tiles = [&](int k0, int buf) {
        uint32_t sa = (uint32_t)__cvta_generic_to_shared(sm + buf * GBUF);
        #pragma unroll
        for (int i = 0; i < 4; ++i) {                 // A tile 128x32
            int idx = tid + i * 256;
            int row = idx >> 3, c4 = idx & 7;
            cp16(sa + (row * GSTR + c4 * 4) * 4,
                 A + (size_t)(m0 + row) * Dc + k0 + c4 * 4);
        }
        #pragma unroll
        for (int i = 0; i < 2; ++i) {                 // W tile 64x32
            int idx = tid + i * 256;
            int row = idx >> 3, c4 = idx & 7;
            cp16(sa + (GW_OFF + row * GSTR + c4 * 4) * 4,
                 W + (size_t)(n0 + row) * Dc + k0 + c4 * 4);
        }
    };

    load_tiles(0, 0);
    cp_commit();

    const int NIT = Dc / GBK;   // 16
    for (int it = 0; it < NIT; ++it) {
        if (it + 1 < NIT) {
            load_tiles((it + 1) * GBK, (it + 1) & 1);
            cp_commit();
            asm volatile("cp.async.wait_group 1;" ::: "memory");
        } else {
            asm volatile("cp.async.wait_group 0;" ::: "memory");
        }
        __syncthreads();

        const float* As = sm + (it & 1) * GBUF;
        const float* Ws = As + GW_OFF;

        #pragma unroll
        for (int kk = 0; kk < 4; ++kk) {
            uint32_t af[2][4], bf[4][2];
            #pragma unroll
            for (int mt = 0; mt < 2; ++mt) {
                const float* p = As + (wm + mt * 16 + g) * GSTR + kk * 8 + t;
                af[mt][0] = f2tf(p[0]);
                af[mt][1] = f2tf(p[8 * GSTR]);
                af[mt][2] = f2tf(p[4]);
                af[mt][3] = f2tf(p[8 * GSTR + 4]);
            }
            #pragma unroll
            for (int nt = 0; nt < 4; ++nt) {
                const float* p = Ws + (wn + nt * 8 + g) * GSTR + kk * 8 + t;
                bf[nt][0] = f2tf(p[0]);
                bf[nt][1] = f2tf(p[4]);
            }
            #pragma unroll
            for (int mt = 0; mt < 2; ++mt)
                #pragma unroll
                for (int nt = 0; nt < 4; ++nt)
                    mma_tf32(acc[mt][nt], af[mt], bf[nt]);
        }
        __syncthreads();
    }

    #pragma unroll
    for (int mt = 0; mt < 2; ++mt) {
        int r0 = m0 + wm + mt * 16 + g;
        #pragma unroll
        for (int nt = 0; nt < 4; ++nt) {
            int col = n0 + wn + nt * 8 + 2 * t;
            float2 b2 = *(const float2*)(bias + col);
            float2 v0 = {acc[mt][nt][0] + b2.x, acc[mt][nt][1] + b2.y};
            float2 v1 = {acc[mt][nt][2] + b2.x, acc[mt][nt][3] + b2.y};
            *(float2*)(C + (size_t)r0 * Dc + col)       = v0;
            *(float2*)(C + (size_t)(r0 + 8) * Dc + col) = v1;
        }
    }
}

// ---------------------------------------------------------------------------
// Causal flash attention, tf32 mma. One CTA = (bh, 64 q rows), 128 threads,
// warp w owns q rows [w*16, w*16+16). Q frags register-resident.
// ---------------------------------------------------------------------------
#define ASTRd 68                       // 68 mod 32 == 4 -> conflict-free frags
#define ATILE (64*ASTRd)               // 4352 floats
#define AV_OFF (2*ATILE)
#define AP_OFF (4*ATILE)
#define ATT_SMEM (5*ATILE*4)           // 87040 bytes

__global__ __launch_bounds__(128) void attn_tf32(
    const float* __restrict__ Q, const float* __restrict__ K,
    const float* __restrict__ V, float* __restrict__ X)
{
    extern __shared__ float sm[];
    float* Ks0 = sm;                   // [2][64*ASTRd]
    float* Vs0 = sm + AV_OFF;          // [2][64*ASTRd]
    float* Ps  = sm + AP_OFF;          // [64*ASTRd], also Q staging

    const int tid  = threadIdx.x;
    const int lane = tid & 31, warp = tid >> 5;
    const int g = lane >> 2, t = lane & 3;
    const int q0 = blockIdx.x * 64;
    const int bh = blockIdx.y, b = bh >> 3, h = bh & 7;

    const size_t base = (size_t)b * Sc * Dc + (size_t)h * 64;
    const float* Qb = Q + base;
    const float* Kb = K + base;
    const float* Vb = V + base;

    const int ntile = q0 / 64 + 1;

    auto load_kv = [&](int kt, int buf) {
        uint32_t sk = (uint32_t)__cvta_generic_to_shared(Ks0 + buf * ATILE);
        uint32_t sv = (uint32_t)__cvta_generic_to_shared(Vs0 + buf * ATILE);
        int k0 = kt * 64;
        #pragma unroll
        for (int i = 0; i < 8; ++i) {
            int idx = tid + i * 128;
            int row = idx >> 4, c4 = idx & 15;
            cp16(sk + (row * ASTRd + c4 * 4) * 4, Kb + (size_t)(k0 + row) * Dc + c4 * 4);
            cp16(sv + (row * ASTRd + c4 * 4) * 4, Vb + (size_t)(k0 + row) * Dc + c4 * 4);
        }
    };

    load_kv(0, 0);
    cp_commit();

    // stage Q tile -> Ps, extract fragments (kept in regs for whole loop)
    for (int i = tid; i < 64 * 16; i += 128) {
        int row = i >> 4, c4 = i & 15;
        *(float4*)(Ps + row * ASTRd + c4 * 4) =
            *(const float4*)(Qb + (size_t)(q0 + row) * Dc + c4 * 4);
    }
    __syncthreads();
    uint32_t qf[8][4];
    {
        const float* p = Ps + (warp * 16 + g) * ASTRd + t;
        #pragma unroll
        for (int ks = 0; ks < 8; ++ks) {
            qf[ks][0] = f2tf(p[ks * 8]);
            qf[ks][1] = f2tf(p[8 * ASTRd + ks * 8]);
            qf[ks][2] = f2tf(p[ks * 8 + 4]);
            qf[ks][3] = f2tf(p[8 * ASTRd + ks * 8 + 4]);
        }
    }
    __syncthreads();   // Ps free for P tiles

    float oacc[8][4] = {};
    float mA = -1e30f, mB = -1e30f, lA = 0.f, lB = 0.f;

    for (int kt = 0; kt < ntile; ++kt) {
        if (kt + 1 < ntile) {
            load_kv(kt + 1, (kt + 1) & 1);
            cp_commit();
            asm volatile("cp.async.wait_group 1;" ::: "memory");
        } else {
            asm volatile("cp.async.wait_group 0;" ::: "memory");
        }
        __syncthreads();

        const float* Ksb = Ks0 + (kt & 1) * ATILE;
        const float* Vsb = Vs0 + (kt & 1) * ATILE;

        // S = Q K^T  (16 x 64 per warp)
        float s[8][4] = {};
        #pragma unroll
        for (int nt = 0; nt < 8; ++nt) {
            const float* kp = Ksb + (nt * 8 + g) * ASTRd + t;
            #pragma unroll
            for (int ks = 0; ks < 8; ++ks) {
                uint32_t bb[2] = { f2tf(kp[ks * 8]), f2tf(kp[ks * 8 + 4]) };
                mma_tf32(s[nt], qf[ks], bb);
            }
        }

        // scale + (diag) mask + row max
        const int k0 = kt * 64;
        const int rowA = q0 + warp * 16 + g;
        float tmaxA = -1e30f, tmaxB = -1e30f;
        #pragma unroll
        for (int nt = 0; nt < 8; ++nt) {
            #pragma unroll
            for (int j = 0; j < 4; ++j) s[nt][j] *= 0.125f;
            if (kt == ntile - 1) {     // diagonal tile: causal mask
                int c0 = k0 + nt * 8 + 2 * t;
                if (c0     > rowA)     s[nt][0] = -1e9f;
                if (c0 + 1 > rowA)     s[nt][1] = -1e9f;
                if (c0     > rowA + 8) s[nt][2] = -1e9f;
                if (c0 + 1 > rowA + 8) s[nt][3] = -1e9f;
            }
            tmaxA = fmaxf(tmaxA, fmaxf(s[nt][0], s[nt][1]));
            tmaxB = fmaxf(tmaxB, fmaxf(s[nt][2], s[nt][3]));
        }
        tmaxA = fmaxf(tmaxA, __shfl_xor_sync(0xffffffffu, tmaxA, 1));
        tmaxA = fmaxf(tmaxA, __shfl_xor_sync(0xffffffffu, tmaxA, 2));
        tmaxB = fmaxf(tmaxB, __shfl_xor_sync(0xffffffffu, tmaxB, 1));
        tmaxB = fmaxf(tmaxB, __shfl_xor_sync(0xffffffffu, tmaxB, 2));

        const float mAn = fmaxf(mA, tmaxA), mBn = fmaxf(mB, tmaxB);
        const float aA = __expf(mA - mAn),  aB = __expf(mB - mBn);
        float psA = 0.f, psB = 0.f;
        #pragma unroll
        for (int nt = 0; nt < 8; ++nt) {
            s[nt][0] = __expf(s[nt][0] - mAn);
            s[nt][1] = __expf(s[nt][1] - mAn);
            s[nt][2] = __expf(s[nt][2] - mBn);
            s[nt][3] = __expf(s[nt][3] - mBn);
            psA += s[nt][0] + s[nt][1];
            psB += s[nt][2] + s[nt][3];
        }
        psA += __shfl_xor_sync(0xffffffffu, psA, 1);
        psA += __shfl_xor_sync(0xffffffffu, psA, 2);
        psB += __shfl_xor_sync(0xffffffffu, psB, 1);
        psB += __shfl_xor_sync(0xffffffffu, psB, 2);
        lA = lA * aA + psA;  mA = mAn;
        lB = lB * aB + psB;  mB = mBn;

        #pragma unroll
        for (int nt = 0; nt < 8; ++nt) {
            oacc[nt][0] *= aA; oacc[nt][1] *= aA;
            oacc[nt][2] *= aB; oacc[nt][3] *= aB;
        }

        // P -> smem (warp-private rows), then PV
        {
            float* pp = Ps + (warp * 16 + g) * ASTRd + 2 * t;
            #pragma unroll
            for (int nt = 0; nt < 8; ++nt) {
                pp[nt * 8]                 = s[nt][0];
                pp[nt * 8 + 1]             = s[nt][1];
                pp[8 * ASTRd + nt * 8]     = s[nt][2];
                pp[8 * ASTRd + nt * 8 + 1] = s[nt][3];
            }
        }
        __syncwarp();
        {
            const float* p = Ps + (warp * 16 + g) * ASTRd + t;
            #pragma unroll
            for (int ks = 0; ks < 8; ++ks) {
                uint32_t pf[4];
                pf[0] = f2tf(p[ks * 8]);
                pf[1] = f2tf(p[8 * ASTRd + ks * 8]);
                pf[2] = f2tf(p[ks * 8 + 4]);
                pf[3] = f2tf(p[8 * ASTRd + ks * 8 + 4]);
                #pragma unroll
                for (int nt = 0; nt < 8; ++nt) {
                    const float* vp = Vsb + (ks * 8 + t) * ASTRd + nt * 8 + g;
                    uint32_t bb[2] = { f2tf(vp[0]), f2tf(vp[4 * ASTRd]) };
                    mma_tf32(oacc[nt], pf, bb);
                }
            }
        }
        __syncthreads();   // everyone done with Ks/Vs buffer + Ps
    }

    const float iA = 1.f / lA, iB = 1.f / lB;
    float* xr = X + ((size_t)b * Sc + q0 + warp * 16 + g) * Dc + (size_t)h * 64;
    #pragma unroll
    for (int nt = 0; nt < 8; ++nt) {
        float2 v0 = {oacc[nt][0] * iA, oacc[nt][1] * iA};
        float2 v1 = {oacc[nt][2] * iB, oacc[nt][3] * iB};
        *(float2*)(xr + nt * 8 + 2 * t)          = v0;
        *(float2*)(xr + 8 * Dc + nt * 8 + 2 * t) = v1;
    }
}

// ---------------------------------------------------------------------------
// Launch
// ---------------------------------------------------------------------------
extern "C" void kernel_launch(void* const* d_in, const int* in_sizes, int n_in,
                              void* d_out, int out_size)
{
    const float* query = (const float*)d_in[0];
    const float* key_  = (const float*)d_in[1];
    const float* value = (const float*)d_in[2];
    // d_in[3] = mask (deterministic tril) -> causal indexing
    const float* Wq = (const float*)d_in[4];
    const float* bq = (const float*)d_in[5];
    const float* Wk = (const float*)d_in[6];
    const float* bk = (const float*)d_in[7];
    const float* Wv = (const float*)d_in[8];
    const float* bv = (const float*)d_in[9];
    const float* Wo = (const float*)d_in[10];
    const float* bo = (const float*)d_in[11];
    float* out = (float*)d_out;

    float *q_buf, *k_buf, *v_buf, *x_buf;
    cudaGetSymbolAddress((void**)&q_buf, g_q);
    cudaGetSymbolAddress((void**)&k_buf, g_k);
    cudaGetSymbolAddress((void**)&v_buf, g_v);
    cudaGetSymbolAddress((void**)&x_buf, g_x);

    cudaFuncSetAttribute(gemm_tf32,
                         cudaFuncAttributeMaxDynamicSharedMemorySize, GEMM_SMEM);
    cudaFuncSetAttribute(attn_tf32,
                         cudaFuncAttributeMaxDynamicSharedMemorySize, ATT_SMEM);

    dim3 ggrid(Dc / GBN, (Bc * Sc) / GBM);   // (8, 32)
    gemm_tf32<<<ggrid, 256, GEMM_SMEM>>>(query, Wq, bq, q_buf);
    gemm_tf32<<<ggrid, 256, GEMM_SMEM>>>(key_,  Wk, bk, k_buf);
    gemm_tf32<<<ggrid, 256, GEMM_SMEM>>>(value, Wv, bv, v_buf);

    dim3 agrid(Sc / 64, Bc * Hc);            // (32, 16)
    attn_tf32<<<agrid, 128, ATT_SMEM>>>(q_buf, k_buf, v_buf, x_buf);

    gemm_tf32<<<ggrid, 256, GEMM_SMEM>>>(x_buf, Wo, bo, out);
}